// round 8
// baseline (speedup 1.0000x reference)
#include <cuda_runtime.h>
#include <cuda_fp16.h>

#define TL   8192
#define CC   256
#define BB   8
#define KTOT 768
#define KC   64
#define NCHK 12
#define NTHR 256
#define NSTG 4

typedef unsigned u32;
typedef unsigned short u16;

// ---------------- device scratch ----------------
// weights pre-packed in mma A-fragment order:
// [iter][mt][wm(2)][mf(4)][kc][s][lane] -> uint4 (8 fp16 = one m16k16 A fragment per lane)
__device__ uint4 g_w1f[3*2*2*4*12*4*32];
__device__ uint4 g_w2f[3*2*2*4*12*4*32];
__device__ u16 g_xh[BB*TL*CC];   // fp16(lrelu(x)), [b][t][ch]
__device__ u16 g_yh[BB*TL*CC];   // fp16(lrelu(stage1 out))

// ---------------- helpers ----------------
__device__ __forceinline__ u32 sm2u(const void* p) {
    u32 a;
    asm("{ .reg .u64 t; cvta.to.shared.u64 t, %1; cvt.u32.u64 %0, t; }" : "=r"(a) : "l"(p));
    return a;
}
__device__ __forceinline__ void cpa16(u32 s, const void* g, u32 sz) {
    asm volatile("cp.async.cg.shared.global [%0], [%1], 16, %2;" :: "r"(s), "l"(g), "r"(sz));
}
__device__ __forceinline__ void cpa_commit() { asm volatile("cp.async.commit_group;"); }
__device__ __forceinline__ void cpa_wait0()  { asm volatile("cp.async.wait_group 0;"); }
__device__ __forceinline__ void cpa_wait1()  { asm volatile("cp.async.wait_group 1;"); }
__device__ __forceinline__ void cpa_wait2()  { asm volatile("cp.async.wait_group 2;"); }

__device__ __forceinline__ void ldm4(u32 addr, u32* r) {
    asm volatile("ldmatrix.sync.aligned.m8n8.x4.shared.b16 {%0,%1,%2,%3}, [%4];"
                 : "=r"(r[0]), "=r"(r[1]), "=r"(r[2]), "=r"(r[3]) : "r"(addr));
}
__device__ __forceinline__ void mma16816(float* d, const u32* a, const u32* b) {
    asm volatile("mma.sync.aligned.m16n8k16.row.col.f32.f16.f16.f32 "
                 "{%0,%1,%2,%3}, {%4,%5,%6,%7}, {%8,%9}, {%0,%1,%2,%3};"
                 : "+f"(d[0]), "+f"(d[1]), "+f"(d[2]), "+f"(d[3])
                 : "r"(a[0]), "r"(a[1]), "r"(a[2]), "r"(a[3]), "r"(b[0]), "r"(b[1]));
}
__device__ __forceinline__ u16 h16(float v) { return __half_as_ushort(__float2half_rn(v)); }
__device__ __forceinline__ float lrelu(float v) { return fmaxf(v, 0.1f * v); }

#define BUFSZ 16384   // one B tile: 128 t-rows x 64 ch fp16

// ---------------- prep: pack weights into A-fragment order ----------------
__global__ void prep_w(const float* __restrict__ WC, const float* __restrict__ WP,
                       const float* __restrict__ WF, const float* __restrict__ WA) {
    int id = blockIdx.x * 256 + threadIdx.x;
    if (id >= 2 * 3 * 2 * 2 * 4 * 12 * 4 * 32) return;   // 147456
    int lane = id & 31; int rest = id >> 5;
    int s  = rest & 3;  rest >>= 2;
    int kc = rest % 12; rest /= 12;
    int mf = rest & 3;  rest >>= 2;
    int wm = rest & 1;  rest >>= 1;
    int mt = rest & 1;  rest >>= 1;
    int i = rest % 3, stage = rest / 3;

    int oc0 = mt * 128 + wm * 64 + mf * 16 + (lane >> 2);
    int k0  = kc * 64 + s * 16 + (lane & 3) * 2;

    float w[2][2][2];   // [oc +0/+8][k +0/+8][k +0/+1]
#pragma unroll
    for (int ro = 0; ro < 2; ++ro)
#pragma unroll
        for (int ko = 0; ko < 2; ++ko)
#pragma unroll
            for (int kk = 0; kk < 2; ++kk) {
                int oc = oc0 + ro * 8;
                int k  = k0 + ko * 8 + kk;
                int sec = k >> 8, ch = k & 255;
                float v;
                if (stage == 0) {
                    const float* W = (sec == 0) ? WC : (sec == 1) ? WP : WF;
                    v = W[i * 65536 + oc * 256 + ch];
                } else {
                    v = WA[(i * 65536 + oc * 256 + ch) * 3 + sec];
                }
                w[ro][ko][kk] = v;
            }
    uint4 out;
    out.x = (u32)h16(w[0][0][0]) | ((u32)h16(w[0][0][1]) << 16);
    out.y = (u32)h16(w[1][0][0]) | ((u32)h16(w[1][0][1]) << 16);
    out.z = (u32)h16(w[0][1][0]) | ((u32)h16(w[0][1][1]) << 16);
    out.w = (u32)h16(w[1][1][0]) | ((u32)h16(w[1][1][1]) << 16);
    int dst = (((((i * 2 + mt) * 2 + wm) * 4 + mf) * 12 + kc) * 4 + s) * 32 + lane;
    if (stage == 0) g_w1f[dst] = out; else g_w2f[dst] = out;
}

// ---------------- prex: lrelu + fp16 + transpose x -> g_xh [b][t][ch] (once) ----------------
__global__ __launch_bounds__(256) void prex(const float* __restrict__ xo) {
    __shared__ u16 s_h[32 * 264];
    int b = blockIdx.y, t0 = blockIdx.x * 32;
    int tid = threadIdx.x;
    int chl = tid >> 3, tw = tid & 7;
    for (int cp = 0; cp < 8; ++cp) {
        int ch = cp * 32 + chl;
        const float4 v = *(const float4*)(xo + ((size_t)(b * 256 + ch)) * TL + t0 + tw * 4);
        float vv[4] = {v.x, v.y, v.z, v.w};
#pragma unroll
        for (int j = 0; j < 4; ++j)
            s_h[(tw * 4 + j) * 264 + ch] = h16(lrelu(vv[j]));
    }
    __syncthreads();
    u32* gh = (u32*)g_xh;
    const u32* sh = (const u32*)s_h;
    for (int i = tid; i < 32 * 128; i += 256) {
        int t = i >> 7, j = i & 127;
        gh[((size_t)(b * TL + t0 + t)) * 128 + j] = sh[t * 132 + j];
    }
}

// ---------------- B producer: one 128x64ch fp16 tile via cp.async ----------------
__device__ __forceinline__ void issueB(u32 sbase, const u16* xh, int mode, int kc,
                                       int b, int t0, const int* s_ip, const int* s_if, int tid) {
    int sec = kc >> 2, ch0 = (kc & 3) << 6;
#pragma unroll
    for (int i = 0; i < 4; ++i) {
        int id = tid + i * NTHR;               // 0..1023
        int r = id >> 3, u = id & 7;
        int st; u32 sz = 16;
        if (mode == 0) {       // k1: xt / xP / xF
            st = (sec == 0) ? (t0 + r) : ((sec == 1) ? s_ip[r] : s_if[r]);
            if (st < 0) { st = 0; sz = 0; }
        } else {               // k2: conv3 taps
            st = t0 + r - 1 + sec;
            if (st < 0 || st >= TL) { st = 0; sz = 0; }
        }
        const u16* src = xh + ((size_t)(b * TL + st)) * CC + ch0 + u * 8;
        u32 dst = sbase + r * 128 + ((u ^ (r & 7)) << 4);
        cpa16(dst, src, sz);
    }
}

// ---------------- MMA core: warp tile 64x32 (2x4 warp grid), A from gmem regs ----------------
// wp points at this warp's (kc) block: element (mf, s) at wp[mf*1536 + s*32]
__device__ __forceinline__ void compute_chunk(u32 base, const int* boff, const int* bsw,
                                              int ubsel, const uint4* __restrict__ wp,
                                              float acc[4][4][4]) {
    uint4 a0[4], a1[4];
#pragma unroll
    for (int mf = 0; mf < 4; ++mf) a0[mf] = wp[mf * 1536];
#pragma unroll
    for (int s = 0; s < 4; ++s) {
        uint4* acur = (s & 1) ? a1 : a0;
        uint4* anxt = (s & 1) ? a0 : a1;
        if (s < 3) {
#pragma unroll
            for (int mf = 0; mf < 4; ++mf) anxt[mf] = wp[mf * 1536 + (s + 1) * 32];
        }
        u32 bh[2][4];
#pragma unroll
        for (int nf = 0; nf < 2; ++nf) {
            u32 ub = (u32)(((2 * s + ubsel) ^ bsw[nf]) << 4);
            ldm4(base + boff[nf] + ub, bh[nf]);
        }
#pragma unroll
        for (int mf = 0; mf < 4; ++mf) {
            const u32* a = (const u32*)&acur[mf];
#pragma unroll
            for (int nb = 0; nb < 4; ++nb)
                mma16816(acc[mf][nb], a, &bh[nb >> 1][(nb & 1) * 2]);
        }
    }
}

__device__ __forceinline__ void bfrag_setup(int wn, int lid, int* boff, int* bsw) {
#pragma unroll
    for (int nf = 0; nf < 2; ++nf) {
        int r = wn * 32 + nf * 16 + (lid & 7) + 8 * (lid >> 4);
        boff[nf] = r * 128; bsw[nf] = r & 7;
    }
}

// 4-stage pipelined main loop
#define GEMM_LOOP(WF, XSRC, MODE)                                                   \
    {                                                                               \
        issueB(sb,             XSRC, MODE, 0, b, t0, s_ip, s_if, tid); cpa_commit();\
        issueB(sb + BUFSZ,     XSRC, MODE, 1, b, t0, s_ip, s_if, tid); cpa_commit();\
        issueB(sb + 2 * BUFSZ, XSRC, MODE, 2, b, t0, s_ip, s_if, tid); cpa_commit();\
        for (int kc = 0; kc < NCHK; ++kc) {                                         \
            if (kc <= NCHK - 3)      cpa_wait2();                                   \
            else if (kc == NCHK - 2) cpa_wait1();                                   \
            else                     cpa_wait0();                                   \
            __syncthreads();                                                        \
            if (kc + 3 < NCHK) {                                                    \
                issueB(sb + ((kc + 3) & 3) * BUFSZ, XSRC, MODE, kc + 3, b, t0,      \
                       s_ip, s_if, tid);                                            \
                cpa_commit();                                                       \
            }                                                                       \
            compute_chunk(sb + (kc & 3) * BUFSZ, boff, bsw, ubsel,                  \
                          WF + wbase + kc * 128 + lid, acc);                        \
        }                                                                           \
    }

// ---------------- stage 1 GEMM kernel ----------------
__global__ __launch_bounds__(NTHR, 2)
void k1(const float* __restrict__ dfac, const float* __restrict__ bC,
        const float* __restrict__ bP, const float* __restrict__ bF,
        int iter, float dilation) {
    extern __shared__ __align__(1024) unsigned char dynsm[];
    __shared__ int s_ip[128], s_if[128];

    const int tid = threadIdx.x, wid = tid >> 5, lid = tid & 31;
    const int wm = wid & 1, wn = wid >> 1;
    const int b = blockIdx.z, mt = blockIdx.y, t0 = blockIdx.x * 128;
    const u32 sb = sm2u(dynsm);
    const int wbase = ((iter * 2 + mt) * 2 + wm) * 6144;

    if (tid < 128) {
        int t = t0 + tid;
        float dil = dfac[b * TL + t] * dilation;
        int ip = __float2int_rn((float)t - dil);
        int iF = __float2int_rn((float)t + dil);
        s_ip[tid] = (ip >= 0) ? ip : -1;
        s_if[tid] = (iF < TL) ? iF : -1;
    }
    __syncthreads();

    int boff[2], bsw[2];
    int ubsel = (lid >> 3) & 1;
    bfrag_setup(wn, lid, boff, bsw);

    float acc[4][4][4];
#pragma unroll
    for (int a = 0; a < 4; ++a)
#pragma unroll
        for (int c = 0; c < 4; ++c)
#pragma unroll
            for (int d = 0; d < 4; ++d) acc[a][c][d] = 0.f;

    GEMM_LOOP(g_w1f, g_xh, 0)

    // epilogue: bias + lrelu + fp16, transpose via smem, store [t][ch] plane
    __syncthreads();
    u16* ep = (u16*)dynsm;   // [128 cols(t)][132 rows(oc)] u16
    int gq = lid >> 2, cq = 2 * (lid & 3);
#pragma unroll
    for (int mf = 0; mf < 4; ++mf) {
        int r0 = wm * 64 + mf * 16 + gq, r1 = r0 + 8;
        int g0 = mt * 128 + r0, g1 = mt * 128 + r1;
        float bs0 = bC[g0] + bP[g0] + bF[g0];
        float bs1 = bC[g1] + bP[g1] + bF[g1];
#pragma unroll
        for (int nb = 0; nb < 4; ++nb) {
            int c = wn * 32 + nb * 8 + cq;
            const float* a = acc[mf][nb];
            ep[c * 132 + r0]       = h16(lrelu(a[0] + bs0));
            ep[(c + 1) * 132 + r0] = h16(lrelu(a[1] + bs0));
            ep[c * 132 + r1]       = h16(lrelu(a[2] + bs1));
            ep[(c + 1) * 132 + r1] = h16(lrelu(a[3] + bs1));
        }
    }
    __syncthreads();
    u32* yh = (u32*)g_yh;
    const u32* epu = (const u32*)dynsm;
    for (int i = tid; i < 128 * 64; i += NTHR) {
        int t = i >> 6, j = i & 63;
        yh[((size_t)(b * TL + t0 + t)) * 128 + mt * 64 + j] = epu[t * 66 + j];
    }
}

// ---------------- stage 2 GEMM kernel (conv3 + residual + write next-iter xh) ----------------
__global__ __launch_bounds__(NTHR, 2)
void k2(float* __restrict__ xo, const float* __restrict__ bA, int iter) {
    extern __shared__ __align__(1024) unsigned char dynsm[];

    const int tid = threadIdx.x, wid = tid >> 5, lid = tid & 31;
    const int wm = wid & 1, wn = wid >> 1;
    const int b = blockIdx.z, mt = blockIdx.y, t0 = blockIdx.x * 128;
    const u32 sb = sm2u(dynsm);
    const int wbase = ((iter * 2 + mt) * 2 + wm) * 6144;
    const int* s_ip = 0; const int* s_if = 0;   // unused in mode 1

    int boff[2], bsw[2];
    int ubsel = (lid >> 3) & 1;
    bfrag_setup(wn, lid, boff, bsw);

    float acc[4][4][4];
#pragma unroll
    for (int a = 0; a < 4; ++a)
#pragma unroll
        for (int c = 0; c < 4; ++c)
#pragma unroll
            for (int d = 0; d < 4; ++d) acc[a][c][d] = 0.f;

    GEMM_LOOP(g_w2f, g_yh, 1)

    // epilogue: bias + residual -> xo; also lrelu+fp16 transpose -> g_xh (next iter)
    __syncthreads();
    u16* ep = (u16*)dynsm;
    int gq = lid >> 2, cq = 2 * (lid & 3);
#pragma unroll
    for (int mf = 0; mf < 4; ++mf) {
        int r0 = wm * 64 + mf * 16 + gq, r1 = r0 + 8;
        int g0 = mt * 128 + r0, g1 = mt * 128 + r1;
        float bs0 = bA[g0], bs1 = bA[g1];
        float* p0b = xo + ((size_t)(b * CC + g0)) * TL + t0;
        float* p1b = xo + ((size_t)(b * CC + g1)) * TL + t0;
#pragma unroll
        for (int nb = 0; nb < 4; ++nb) {
            int c = wn * 32 + nb * 8 + cq;
            const float* a = acc[mf][nb];
            float2* q0 = (float2*)(p0b + c);
            float2 v0 = *q0;
            v0.x += a[0] + bs0; v0.y += a[1] + bs0;
            *q0 = v0;
            float2* q1 = (float2*)(p1b + c);
            float2 v1 = *q1;
            v1.x += a[2] + bs1; v1.y += a[3] + bs1;
            *q1 = v1;
            ep[c * 132 + r0]       = h16(lrelu(v0.x));
            ep[(c + 1) * 132 + r0] = h16(lrelu(v0.y));
            ep[c * 132 + r1]       = h16(lrelu(v1.x));
            ep[(c + 1) * 132 + r1] = h16(lrelu(v1.y));
        }
    }
    __syncthreads();
    u32* xh = (u32*)g_xh;
    const u32* epu = (const u32*)dynsm;
    for (int i = tid; i < 128 * 64; i += NTHR) {
        int t = i >> 6, j = i & 63;
        xh[((size_t)(b * TL + t0 + t)) * 128 + mt * 64 + j] = epu[t * 66 + j];
    }
}

// ---------------- launch ----------------
extern "C" void kernel_launch(void* const* d_in, const int* in_sizes, int n_in,
                              void* d_out, int out_size) {
    const float* x  = (const float*)d_in[0];
    const float* d  = (const float*)d_in[1];
    const float* WC = (const float*)d_in[2];
    const float* bC = (const float*)d_in[3];
    const float* WP = (const float*)d_in[4];
    const float* bP = (const float*)d_in[5];
    const float* WF = (const float*)d_in[6];
    const float* bF = (const float*)d_in[7];
    const float* WA = (const float*)d_in[8];
    const float* bA = (const float*)d_in[9];
    float* xo = (float*)d_out;

    cudaMemcpyAsync(xo, x, (size_t)BB * CC * TL * sizeof(float),
                    cudaMemcpyDeviceToDevice);

    prep_w<<<576, 256>>>(WC, WP, WF, WA);

    const int DSMEM = NSTG * BUFSZ;   // 64 KB
    cudaFuncSetAttribute((const void*)k1, cudaFuncAttributeMaxDynamicSharedMemorySize, DSMEM);
    cudaFuncSetAttribute((const void*)k2, cudaFuncAttributeMaxDynamicSharedMemorySize, DSMEM);

    dim3 gprex(TL / 32, BB);
    dim3 grid(TL / 128, 2, BB);
    const float dils[3] = {1.0f, 2.0f, 4.0f};
    prex<<<gprex, 256>>>(xo);
    for (int i = 0; i < 3; ++i) {
        k1<<<grid, NTHR, DSMEM>>>(d, bC + i * 256, bP + i * 256, bF + i * 256, i, dils[i]);
        k2<<<grid, NTHR, DSMEM>>>(xo, bA + i * 256, i);
    }
}

// round 9
// speedup vs baseline: 1.1411x; 1.1411x over previous
#include <cuda_runtime.h>
#include <cuda_fp16.h>

#define TL   8192
#define CC   256
#define BB   8
#define KTOT 768
#define NSUB 12     // 64-wide K sub-chunks (same indexing as R7)
#define NCH2 6      // 128-wide chunks = 2 sub-chunks
#define NTHR 256

typedef unsigned u32;
typedef unsigned short u16;

// ---------------- device scratch ----------------
// weights pre-packed in mma A-fragment order:
// [iter][mt][wm(4)][mf(2)][sub(12)][s(4)][lane] -> uint4
__device__ uint4 g_w1f[3*2*4*2*12*4*32];
__device__ uint4 g_w2f[3*2*4*2*12*4*32];
__device__ u16 g_xh[BB*TL*CC];   // fp16(lrelu(x)), [b][t][ch]
__device__ u16 g_yh[BB*TL*CC];   // fp16(lrelu(stage1 out))

// ---------------- helpers ----------------
__device__ __forceinline__ u32 sm2u(const void* p) {
    u32 a;
    asm("{ .reg .u64 t; cvta.to.shared.u64 t, %1; cvt.u32.u64 %0, t; }" : "=r"(a) : "l"(p));
    return a;
}
__device__ __forceinline__ void cpa16(u32 s, const void* g, u32 sz) {
    asm volatile("cp.async.cg.shared.global [%0], [%1], 16, %2;" :: "r"(s), "l"(g), "r"(sz));
}
__device__ __forceinline__ void cpa_commit() { asm volatile("cp.async.commit_group;"); }
__device__ __forceinline__ void cpa_wait0()  { asm volatile("cp.async.wait_group 0;"); }
__device__ __forceinline__ void cpa_wait1()  { asm volatile("cp.async.wait_group 1;"); }

__device__ __forceinline__ void ldm4(u32 addr, u32* r) {
    asm volatile("ldmatrix.sync.aligned.m8n8.x4.shared.b16 {%0,%1,%2,%3}, [%4];"
                 : "=r"(r[0]), "=r"(r[1]), "=r"(r[2]), "=r"(r[3]) : "r"(addr));
}
__device__ __forceinline__ void mma16816(float* d, const u32* a, const u32* b) {
    asm volatile("mma.sync.aligned.m16n8k16.row.col.f32.f16.f16.f32 "
                 "{%0,%1,%2,%3}, {%4,%5,%6,%7}, {%8,%9}, {%0,%1,%2,%3};"
                 : "+f"(d[0]), "+f"(d[1]), "+f"(d[2]), "+f"(d[3])
                 : "r"(a[0]), "r"(a[1]), "r"(a[2]), "r"(a[3]), "r"(b[0]), "r"(b[1]));
}
__device__ __forceinline__ u16 h16(float v) { return __half_as_ushort(__float2half_rn(v)); }
__device__ __forceinline__ float lrelu(float v) { return fmaxf(v, 0.1f * v); }

#define BUFSZ 16384            // one 128t x 64ch fp16 sub-tile
#define CHKSZ (2 * BUFSZ)      // one 128-K chunk
#define DSMEM (3 * CHKSZ)      // 96 KB, 3-stage

// ---------------- prep: pack weights into A-fragment order (R7 layout) ----------------
__global__ void prep_w(const float* __restrict__ WC, const float* __restrict__ WP,
                       const float* __restrict__ WF, const float* __restrict__ WA) {
    int id = blockIdx.x * 256 + threadIdx.x;
    if (id >= 2 * 3 * 2 * 4 * 2 * 12 * 4 * 32) return;   // 147456
    int lane = id & 31; int rest = id >> 5;
    int s  = rest & 3;  rest >>= 2;
    int kc = rest % 12; rest /= 12;
    int mf = rest & 1;  rest >>= 1;
    int wm = rest & 3;  rest >>= 2;
    int mt = rest & 1;  rest >>= 1;
    int i = rest % 3, stage = rest / 3;

    int oc0 = mt * 128 + wm * 32 + mf * 16 + (lane >> 2);
    int k0  = kc * 64 + s * 16 + (lane & 3) * 2;

    float w[2][2][2];
#pragma unroll
    for (int ro = 0; ro < 2; ++ro)
#pragma unroll
        for (int ko = 0; ko < 2; ++ko)
#pragma unroll
            for (int kk = 0; kk < 2; ++kk) {
                int oc = oc0 + ro * 8;
                int k  = k0 + ko * 8 + kk;
                int sec = k >> 8, ch = k & 255;
                float v;
                if (stage == 0) {
                    const float* W = (sec == 0) ? WC : (sec == 1) ? WP : WF;
                    v = W[i * 65536 + oc * 256 + ch];
                } else {
                    v = WA[(i * 65536 + oc * 256 + ch) * 3 + sec];
                }
                w[ro][ko][kk] = v;
            }
    uint4 out;
    out.x = (u32)h16(w[0][0][0]) | ((u32)h16(w[0][0][1]) << 16);
    out.y = (u32)h16(w[1][0][0]) | ((u32)h16(w[1][0][1]) << 16);
    out.z = (u32)h16(w[0][1][0]) | ((u32)h16(w[0][1][1]) << 16);
    out.w = (u32)h16(w[1][1][0]) | ((u32)h16(w[1][1][1]) << 16);
    int dst = (((((i * 2 + mt) * 4 + wm) * 2 + mf) * 12 + kc) * 4 + s) * 32 + lane;
    if (stage == 0) g_w1f[dst] = out; else g_w2f[dst] = out;
}

// ---------------- prex: lrelu + fp16 + transpose x -> g_xh [b][t][ch] (once) ----------------
__global__ __launch_bounds__(256) void prex(const float* __restrict__ xo) {
    __shared__ u16 s_h[32 * 264];
    int b = blockIdx.y, t0 = blockIdx.x * 32;
    int tid = threadIdx.x;
    int chl = tid >> 3, tw = tid & 7;
    for (int cp = 0; cp < 8; ++cp) {
        int ch = cp * 32 + chl;
        const float4 v = *(const float4*)(xo + ((size_t)(b * 256 + ch)) * TL + t0 + tw * 4);
        float vv[4] = {v.x, v.y, v.z, v.w};
#pragma unroll
        for (int j = 0; j < 4; ++j)
            s_h[(tw * 4 + j) * 264 + ch] = h16(lrelu(vv[j]));
    }
    __syncthreads();
    u32* gh = (u32*)g_xh;
    const u32* sh = (const u32*)s_h;
    for (int i = tid; i < 32 * 128; i += 256) {
        int t = i >> 7, j = i & 127;
        gh[((size_t)(b * TL + t0 + t)) * 128 + j] = sh[t * 132 + j];
    }
}

// ---------------- B producer: one 128x64ch fp16 sub-tile via cp.async ----------------
// sck = 64-wide sub-chunk index 0..11 (same mapping as R7)
__device__ __forceinline__ void issueB(u32 sbase, const u16* xh, int mode, int sck,
                                       int b, int t0, const int* s_ip, const int* s_if, int tid) {
    int sec = sck >> 2, ch0 = (sck & 3) << 6;
#pragma unroll
    for (int i = 0; i < 4; ++i) {
        int id = tid + i * NTHR;               // 0..1023
        int r = id >> 3, u = id & 7;
        int st; u32 sz = 16;
        if (mode == 0) {       // k1: xt / xP / xF
            st = (sec == 0) ? (t0 + r) : ((sec == 1) ? s_ip[r] : s_if[r]);
            if (st < 0) { st = 0; sz = 0; }
        } else {               // k2: conv3 taps
            st = t0 + r - 1 + sec;
            if (st < 0 || st >= TL) { st = 0; sz = 0; }
        }
        const u16* src = xh + ((size_t)(b * TL + st)) * CC + ch0 + u * 8;
        u32 dst = sbase + r * 128 + ((u ^ (r & 7)) << 4);
        cpa16(dst, src, sz);
    }
}

// ---------------- MMA core: warp tile 32x64 (4x2 warp grid), A from gmem regs ----------------
__device__ __forceinline__ void compute_sub(u32 base, const int* boff, const int* bsw,
                                            int ubsel, const uint4* __restrict__ wp,
                                            float acc[2][8][4]) {
    uint4 af[2][4];
#pragma unroll
    for (int mf = 0; mf < 2; ++mf)
#pragma unroll
        for (int s = 0; s < 4; ++s)
            af[mf][s] = wp[(mf * 12) * 128 + s * 32];   // wp pre-offset by sub
#pragma unroll
    for (int s = 0; s < 4; ++s) {
        u32 bh[4][4];
#pragma unroll
        for (int nf = 0; nf < 4; ++nf) {
            u32 ub = (u32)(((2 * s + ubsel) ^ bsw[nf]) << 4);
            ldm4(base + boff[nf] + ub, bh[nf]);
        }
#pragma unroll
        for (int mf = 0; mf < 2; ++mf) {
            const u32* a = (const u32*)&af[mf][s];
#pragma unroll
            for (int nb = 0; nb < 8; ++nb)
                mma16816(acc[mf][nb], a, &bh[nb >> 1][(nb & 1) * 2]);
        }
    }
}

__device__ __forceinline__ void bfrag_setup(int wn, int lid, int* boff, int* bsw) {
#pragma unroll
    for (int nf = 0; nf < 4; ++nf) {
        int r = wn * 64 + nf * 16 + (lid & 7) + 8 * (lid >> 4);
        boff[nf] = r * 128; bsw[nf] = r & 7;
    }
}

// 3-stage pipelined main loop over 6 double chunks (wait/sync halved vs R7)
#define GEMM_LOOP(WF, XSRC, MODE)                                                    \
    {                                                                                \
        issueB(sb,             XSRC, MODE, 0, b, t0, s_ip, s_if, tid);               \
        issueB(sb + BUFSZ,     XSRC, MODE, 1, b, t0, s_ip, s_if, tid); cpa_commit(); \
        issueB(sb + CHKSZ,         XSRC, MODE, 2, b, t0, s_ip, s_if, tid);           \
        issueB(sb + CHKSZ + BUFSZ, XSRC, MODE, 3, b, t0, s_ip, s_if, tid); cpa_commit(); \
        for (int kc = 0; kc < NCH2; ++kc) {                                          \
            if (kc == NCH2 - 1) cpa_wait0(); else cpa_wait1();                       \
            __syncthreads();                                                         \
            if (kc + 2 < NCH2) {                                                     \
                u32 nb_ = sb + ((kc + 2) % 3) * CHKSZ;                               \
                issueB(nb_,         XSRC, MODE, 2 * kc + 4, b, t0, s_ip, s_if, tid); \
                issueB(nb_ + BUFSZ, XSRC, MODE, 2 * kc + 5, b, t0, s_ip, s_if, tid); \
                cpa_commit();                                                        \
            }                                                                        \
            u32 cb_ = sb + (kc % 3) * CHKSZ;                                         \
            compute_sub(cb_,         boff, bsw, ubsel, WF + wbase + (2 * kc) * 128 + lid, acc);     \
            compute_sub(cb_ + BUFSZ, boff, bsw, ubsel, WF + wbase + (2 * kc + 1) * 128 + lid, acc); \
        }                                                                            \
    }

// ---------------- stage 1 GEMM kernel ----------------
__global__ __launch_bounds__(NTHR, 2)
void k1(const float* __restrict__ dfac, const float* __restrict__ bC,
        const float* __restrict__ bP, const float* __restrict__ bF,
        int iter, float dilation) {
    extern __shared__ __align__(1024) unsigned char dynsm[];
    __shared__ int s_ip[128], s_if[128];

    const int tid = threadIdx.x, wid = tid >> 5, lid = tid & 31;
    const int wm = wid & 3, wn = wid >> 2;
    const int b = blockIdx.z, mt = blockIdx.y, t0 = blockIdx.x * 128;
    const u32 sb = sm2u(dynsm);
    const int wbase = ((iter * 2 + mt) * 4 + wm) * 3072;

    if (tid < 128) {
        int t = t0 + tid;
        float dil = dfac[b * TL + t] * dilation;
        int ip = __float2int_rn((float)t - dil);
        int iF = __float2int_rn((float)t + dil);
        s_ip[tid] = (ip >= 0) ? ip : -1;
        s_if[tid] = (iF < TL) ? iF : -1;
    }
    __syncthreads();

    int boff[4], bsw[4];
    int ubsel = (lid >> 3) & 1;
    bfrag_setup(wn, lid, boff, bsw);

    float acc[2][8][4];
#pragma unroll
    for (int a = 0; a < 2; ++a)
#pragma unroll
        for (int c = 0; c < 8; ++c)
#pragma unroll
            for (int d = 0; d < 4; ++d) acc[a][c][d] = 0.f;

    GEMM_LOOP(g_w1f, g_xh, 0)

    // epilogue: bias + lrelu + fp16, transpose via smem, store [t][ch] plane
    __syncthreads();
    u16* ep = (u16*)dynsm;   // [128 cols(t)][132 rows(oc)] u16
    int gq = lid >> 2, cq = 2 * (lid & 3);
#pragma unroll
    for (int mf = 0; mf < 2; ++mf) {
        int r0 = wm * 32 + mf * 16 + gq, r1 = r0 + 8;
        int g0 = mt * 128 + r0, g1 = mt * 128 + r1;
        float bs0 = bC[g0] + bP[g0] + bF[g0];
        float bs1 = bC[g1] + bP[g1] + bF[g1];
#pragma unroll
        for (int nb = 0; nb < 8; ++nb) {
            int c = wn * 64 + nb * 8 + cq;
            const float* a = acc[mf][nb];
            ep[c * 132 + r0]       = h16(lrelu(a[0] + bs0));
            ep[(c + 1) * 132 + r0] = h16(lrelu(a[1] + bs0));
            ep[c * 132 + r1]       = h16(lrelu(a[2] + bs1));
            ep[(c + 1) * 132 + r1] = h16(lrelu(a[3] + bs1));
        }
    }
    __syncthreads();
    u32* yh = (u32*)g_yh;
    const u32* epu = (const u32*)dynsm;
    for (int i = tid; i < 128 * 64; i += NTHR) {
        int t = i >> 6, j = i & 63;
        yh[((size_t)(b * TL + t0 + t)) * 128 + mt * 64 + j] = epu[t * 66 + j];
    }
}

// ---------------- stage 2 GEMM kernel (conv3 + residual + write next-iter xh) ----------------
__global__ __launch_bounds__(NTHR, 2)
void k2(float* __restrict__ xo, const float* __restrict__ bA, int iter) {
    extern __shared__ __align__(1024) unsigned char dynsm[];

    const int tid = threadIdx.x, wid = tid >> 5, lid = tid & 31;
    const int wm = wid & 3, wn = wid >> 2;
    const int b = blockIdx.z, mt = blockIdx.y, t0 = blockIdx.x * 128;
    const u32 sb = sm2u(dynsm);
    const int wbase = ((iter * 2 + mt) * 4 + wm) * 3072;
    const int* s_ip = 0; const int* s_if = 0;   // unused in mode 1

    int boff[4], bsw[4];
    int ubsel = (lid >> 3) & 1;
    bfrag_setup(wn, lid, boff, bsw);

    float acc[2][8][4];
#pragma unroll
    for (int a = 0; a < 2; ++a)
#pragma unroll
        for (int c = 0; c < 8; ++c)
#pragma unroll
            for (int d = 0; d < 4; ++d) acc[a][c][d] = 0.f;

    GEMM_LOOP(g_w2f, g_yh, 1)

    // epilogue: bias + residual -> xo; also lrelu+fp16 transpose -> g_xh (next iter)
    __syncthreads();
    u16* ep = (u16*)dynsm;
    int gq = lid >> 2, cq = 2 * (lid & 3);
#pragma unroll
    for (int mf = 0; mf < 2; ++mf) {
        int r0 = wm * 32 + mf * 16 + gq, r1 = r0 + 8;
        int g0 = mt * 128 + r0, g1 = mt * 128 + r1;
        float bs0 = bA[g0], bs1 = bA[g1];
        float* p0b = xo + ((size_t)(b * CC + g0)) * TL + t0;
        float* p1b = xo + ((size_t)(b * CC + g1)) * TL + t0;
#pragma unroll
        for (int nb = 0; nb < 8; ++nb) {
            int c = wn * 64 + nb * 8 + cq;
            const float* a = acc[mf][nb];
            float2* q0 = (float2*)(p0b + c);
            float2 v0 = *q0;
            v0.x += a[0] + bs0; v0.y += a[1] + bs0;
            *q0 = v0;
            float2* q1 = (float2*)(p1b + c);
            float2 v1 = *q1;
            v1.x += a[2] + bs1; v1.y += a[3] + bs1;
            *q1 = v1;
            ep[c * 132 + r0]       = h16(lrelu(v0.x));
            ep[(c + 1) * 132 + r0] = h16(lrelu(v0.y));
            ep[c * 132 + r1]       = h16(lrelu(v1.x));
            ep[(c + 1) * 132 + r1] = h16(lrelu(v1.y));
        }
    }
    __syncthreads();
    u32* xh = (u32*)g_xh;
    const u32* epu = (const u32*)dynsm;
    for (int i = tid; i < 128 * 64; i += NTHR) {
        int t = i >> 6, j = i & 63;
        xh[((size_t)(b * TL + t0 + t)) * 128 + mt * 64 + j] = epu[t * 66 + j];
    }
}

// ---------------- launch ----------------
extern "C" void kernel_launch(void* const* d_in, const int* in_sizes, int n_in,
                              void* d_out, int out_size) {
    const float* x  = (const float*)d_in[0];
    const float* d  = (const float*)d_in[1];
    const float* WC = (const float*)d_in[2];
    const float* bC = (const float*)d_in[3];
    const float* WP = (const float*)d_in[4];
    const float* bP = (const float*)d_in[5];
    const float* WF = (const float*)d_in[6];
    const float* bF = (const float*)d_in[7];
    const float* WA = (const float*)d_in[8];
    const float* bA = (const float*)d_in[9];
    float* xo = (float*)d_out;

    cudaMemcpyAsync(xo, x, (size_t)BB * CC * TL * sizeof(float),
                    cudaMemcpyDeviceToDevice);

    prep_w<<<576, 256>>>(WC, WP, WF, WA);

    cudaFuncSetAttribute((const void*)k1, cudaFuncAttributeMaxDynamicSharedMemorySize, DSMEM);
    cudaFuncSetAttribute((const void*)k2, cudaFuncAttributeMaxDynamicSharedMemorySize, DSMEM);

    dim3 gprex(TL / 32, BB);
    dim3 grid(TL / 128, 2, BB);
    const float dils[3] = {1.0f, 2.0f, 4.0f};
    prex<<<gprex, 256>>>(xo);
    for (int i = 0; i < 3; ++i) {
        k1<<<grid, NTHR, DSMEM>>>(d, bC + i * 256, bP + i * 256, bF + i * 256, i, dils[i]);
        k2<<<grid, NTHR, DSMEM>>>(xo, bA + i * 256, i);
    }
}

// round 11
// speedup vs baseline: 1.3472x; 1.1806x over previous
#include <cuda_runtime.h>
#include <cuda_fp16.h>

#define TL   8192
#define CC   256
#define BB   8
#define KTOT 768
#define NSUB 12     // 64-wide K sub-chunks
#define NTHR 256

typedef unsigned u32;
typedef unsigned short u16;

// ---------------- device scratch ----------------
// weights in cp.async-ready A-fragment blocks:
// [iter][mt][sub][wm(4)][mf(2)][s(4)][lane(32)] -> uint4
__device__ uint4 g_w1f[3*2*12*4*2*4*32];
__device__ uint4 g_w2f[3*2*12*4*2*4*32];
__device__ u16 g_xh[BB*TL*CC];   // fp16(lrelu(x)), [b][t][ch]
__device__ u16 g_yh[BB*TL*CC];   // fp16(lrelu(stage1 out))

// ---------------- helpers ----------------
__device__ __forceinline__ u32 sm2u(const void* p) {
    u32 a;
    asm("{ .reg .u64 t; cvta.to.shared.u64 t, %1; cvt.u32.u64 %0, t; }" : "=r"(a) : "l"(p));
    return a;
}
__device__ __forceinline__ void cpa16(u32 s, const void* g, u32 sz) {
    asm volatile("cp.async.cg.shared.global [%0], [%1], 16, %2;" :: "r"(s), "l"(g), "r"(sz));
}
__device__ __forceinline__ void cpa_commit() { asm volatile("cp.async.commit_group;"); }
__device__ __forceinline__ void cpa_wait0()  { asm volatile("cp.async.wait_group 0;"); }
__device__ __forceinline__ void cpa_wait1()  { asm volatile("cp.async.wait_group 1;"); }

__device__ __forceinline__ void ldm4(u32 addr, u32* r) {
    asm volatile("ldmatrix.sync.aligned.m8n8.x4.shared.b16 {%0,%1,%2,%3}, [%4];"
                 : "=r"(r[0]), "=r"(r[1]), "=r"(r[2]), "=r"(r[3]) : "r"(addr));
}
__device__ __forceinline__ void lds128(uint4& v, u32 addr) {
    asm volatile("ld.shared.v4.b32 {%0,%1,%2,%3}, [%4];"
                 : "=r"(v.x), "=r"(v.y), "=r"(v.z), "=r"(v.w) : "r"(addr));
}
__device__ __forceinline__ void mma16816(float* d, const u32* a, const u32* b) {
    asm volatile("mma.sync.aligned.m16n8k16.row.col.f32.f16.f16.f32 "
                 "{%0,%1,%2,%3}, {%4,%5,%6,%7}, {%8,%9}, {%0,%1,%2,%3};"
                 : "+f"(d[0]), "+f"(d[1]), "+f"(d[2]), "+f"(d[3])
                 : "r"(a[0]), "r"(a[1]), "r"(a[2]), "r"(a[3]), "r"(b[0]), "r"(b[1]));
}
__device__ __forceinline__ u16 h16(float v) { return __half_as_ushort(__float2half_rn(v)); }
__device__ __forceinline__ float lrelu(float v) { return fmaxf(v, 0.1f * v); }

#define ASZ   16384            // A fragment block per sub
#define BUFSZ 32768            // stage = A(16K) + B(16K)
#define DSMEM (3 * BUFSZ)      // 96 KB, 3-stage

// ---------------- prep: pack weights into cp.async A-fragment blocks ----------------
__global__ void prep_w(const float* __restrict__ WC, const float* __restrict__ WP,
                       const float* __restrict__ WF, const float* __restrict__ WA) {
    int id = blockIdx.x * 256 + threadIdx.x;
    if (id >= 2 * 3 * 2 * 4 * 2 * 12 * 4 * 32) return;   // 147456
    int lane = id & 31; int rest = id >> 5;
    int s  = rest & 3;  rest >>= 2;
    int kc = rest % 12; rest /= 12;
    int mf = rest & 1;  rest >>= 1;
    int wm = rest & 3;  rest >>= 2;
    int mt = rest & 1;  rest >>= 1;
    int i = rest % 3, stage = rest / 3;

    int oc0 = mt * 128 + wm * 32 + mf * 16 + (lane >> 2);
    int k0  = kc * 64 + s * 16 + (lane & 3) * 2;

    float w[2][2][2];
#pragma unroll
    for (int ro = 0; ro < 2; ++ro)
#pragma unroll
        for (int ko = 0; ko < 2; ++ko)
#pragma unroll
            for (int kk = 0; kk < 2; ++kk) {
                int oc = oc0 + ro * 8;
                int k  = k0 + ko * 8 + kk;
                int sec = k >> 8, ch = k & 255;
                float v;
                if (stage == 0) {
                    const float* W = (sec == 0) ? WC : (sec == 1) ? WP : WF;
                    v = W[i * 65536 + oc * 256 + ch];
                } else {
                    v = WA[(i * 65536 + oc * 256 + ch) * 3 + sec];
                }
                w[ro][ko][kk] = v;
            }
    uint4 out;
    out.x = (u32)h16(w[0][0][0]) | ((u32)h16(w[0][0][1]) << 16);
    out.y = (u32)h16(w[1][0][0]) | ((u32)h16(w[1][0][1]) << 16);
    out.z = (u32)h16(w[0][1][0]) | ((u32)h16(w[0][1][1]) << 16);
    out.w = (u32)h16(w[1][1][0]) | ((u32)h16(w[1][1][1]) << 16);
    // dst: [i][mt][kc][wm][mf][s][lane]
    int dst = (((((i * 2 + mt) * 12 + kc) * 4 + wm) * 2 + mf) * 4 + s) * 32 + lane;
    if (stage == 0) g_w1f[dst] = out; else g_w2f[dst] = out;
}

// ---------------- prex: lrelu + fp16 + transpose x -> g_xh [b][t][ch] (once) ----------------
__global__ __launch_bounds__(256) void prex(const float* __restrict__ xin) {
    __shared__ u16 s_h[32 * 264];
    int b = blockIdx.y, t0 = blockIdx.x * 32;
    int tid = threadIdx.x;
    int chl = tid >> 3, tw = tid & 7;
    for (int cp = 0; cp < 8; ++cp) {
        int ch = cp * 32 + chl;
        const float4 v = *(const float4*)(xin + ((size_t)(b * 256 + ch)) * TL + t0 + tw * 4);
        float vv[4] = {v.x, v.y, v.z, v.w};
#pragma unroll
        for (int j = 0; j < 4; ++j)
            s_h[(tw * 4 + j) * 264 + ch] = h16(lrelu(vv[j]));
    }
    __syncthreads();
    u32* gh = (u32*)g_xh;
    const u32* sh = (const u32*)s_h;
    for (int i = tid; i < 32 * 128; i += 256) {
        int t = i >> 7, j = i & 127;
        gh[((size_t)(b * TL + t0 + t)) * 128 + j] = sh[t * 132 + j];
    }
}

// ---------------- producers ----------------
__device__ __forceinline__ void issueA(u32 sbase, const uint4* __restrict__ wsrc, int tid) {
#pragma unroll
    for (int i = 0; i < 4; ++i) {
        int id = tid + i * NTHR;               // 0..1023
        cpa16(sbase + id * 16, wsrc + id, 16);
    }
}
__device__ __forceinline__ void issueB(u32 sbase, const u16* xh, int mode, int sck,
                                       int b, int t0, const int* s_ip, const int* s_if, int tid) {
    int sec = sck >> 2, ch0 = (sck & 3) << 6;
#pragma unroll
    for (int i = 0; i < 4; ++i) {
        int id = tid + i * NTHR;               // 0..1023
        int r = id >> 3, u = id & 7;
        int st; u32 sz = 16;
        if (mode == 0) {       // k1: xt / xP / xF
            st = (sec == 0) ? (t0 + r) : ((sec == 1) ? s_ip[r] : s_if[r]);
            if (st < 0) { st = 0; sz = 0; }
        } else {               // k2: conv3 taps
            st = t0 + r - 1 + sec;
            if (st < 0 || st >= TL) { st = 0; sz = 0; }
        }
        const u16* src = xh + ((size_t)(b * TL + st)) * CC + ch0 + u * 8;
        u32 dst = sbase + r * 128 + ((u ^ (r & 7)) << 4);
        cpa16(dst, src, sz);
    }
}

// ---------------- MMA core: warp tile 32x64 (4x2 grid), A via LDS.128 ----------------
// aoff = stageA + wm*4096 + lid*16 ; frag(mf,s) at aoff + mf*2048 + s*512
__device__ __forceinline__ void compute_sub(u32 aoff, u32 bbase, const int* boff, const int* bsw,
                                            int ubsel, float acc[2][8][4]) {
    uint4 a0[2], a1[2];
    lds128(a0[0], aoff);
    lds128(a0[1], aoff + 2048);
#pragma unroll
    for (int s = 0; s < 4; ++s) {
        uint4* ac = (s & 1) ? a1 : a0;
        uint4* an = (s & 1) ? a0 : a1;
        if (s < 3) {
            lds128(an[0], aoff + (s + 1) * 512);
            lds128(an[1], aoff + 2048 + (s + 1) * 512);
        }
        u32 bh[4][4];
#pragma unroll
        for (int nf = 0; nf < 4; ++nf) {
            u32 ub = (u32)(((2 * s + ubsel) ^ bsw[nf]) << 4);
            ldm4(bbase + boff[nf] + ub, bh[nf]);
        }
#pragma unroll
        for (int mf = 0; mf < 2; ++mf) {
            const u32* a = (const u32*)&ac[mf];
#pragma unroll
            for (int nb = 0; nb < 8; ++nb)
                mma16816(acc[mf][nb], a, &bh[nb >> 1][(nb & 1) * 2]);
        }
    }
}

__device__ __forceinline__ void bfrag_setup(int wn, int lid, int* boff, int* bsw) {
#pragma unroll
    for (int nf = 0; nf < 4; ++nf) {
        int r = wn * 64 + nf * 16 + (lid & 7) + 8 * (lid >> 4);
        boff[nf] = r * 128; bsw[nf] = r & 7;
    }
}

// 3-stage pipelined loop over 12 subs; both A and B via cp.async
#define GEMM_LOOP(WF, XSRC, MODE)                                                      \
    {                                                                                  \
        issueA(sb,         WF + wbase,        tid);                                    \
        issueB(sb + ASZ,   XSRC, MODE, 0, b, t0, s_ip, s_if, tid); cpa_commit();       \
        issueA(sb + BUFSZ, WF + wbase + 1024, tid);                                    \
        issueB(sb + BUFSZ + ASZ, XSRC, MODE, 1, b, t0, s_ip, s_if, tid); cpa_commit(); \
        for (int kc = 0; kc < NSUB; ++kc) {                                            \
            if (kc == NSUB - 1) cpa_wait0(); else cpa_wait1();                         \
            __syncthreads();                                                           \
            if (kc + 2 < NSUB) {                                                       \
                u32 nb_ = sb + ((kc + 2) % 3) * BUFSZ;                                 \
                issueA(nb_, WF + wbase + (kc + 2) * 1024, tid);                        \
                issueB(nb_ + ASZ, XSRC, MODE, kc + 2, b, t0, s_ip, s_if, tid);         \
                cpa_commit();                                                          \
            }                                                                          \
            u32 cb_ = sb + (kc % 3) * BUFSZ;                                           \
            compute_sub(cb_ + awoff, cb_ + ASZ, boff, bsw, ubsel, acc);                \
        }                                                                              \
    }

// ---------------- stage 1 GEMM kernel ----------------
__global__ __launch_bounds__(NTHR, 2)
void k1(const float* __restrict__ dfac, const float* __restrict__ bC,
        const float* __restrict__ bP, const float* __restrict__ bF,
        int iter, float dilation) {
    extern __shared__ __align__(1024) unsigned char dynsm[];
    __shared__ int s_ip[128], s_if[128];

    const int tid = threadIdx.x, wid = tid >> 5, lid = tid & 31;
    const int wm = wid & 3, wn = wid >> 2;
    const int b = blockIdx.z, mt = blockIdx.y, t0 = blockIdx.x * 128;
    const u32 sb = sm2u(dynsm);
    const int wbase = ((iter * 2 + mt) * 12) * 1024;     // uint4 units
    const u32 awoff = wm * 4096 + lid * 16;

    if (tid < 128) {
        int t = t0 + tid;
        float dil = dfac[b * TL + t] * dilation;
        int ip = __float2int_rn((float)t - dil);
        int iF = __float2int_rn((float)t + dil);
        s_ip[tid] = (ip >= 0) ? ip : -1;
        s_if[tid] = (iF < TL) ? iF : -1;
    }
    __syncthreads();

    int boff[4], bsw[4];
    int ubsel = (lid >> 3) & 1;
    bfrag_setup(wn, lid, boff, bsw);

    float acc[2][8][4];
#pragma unroll
    for (int a = 0; a < 2; ++a)
#pragma unroll
        for (int c = 0; c < 8; ++c)
#pragma unroll
            for (int d = 0; d < 4; ++d) acc[a][c][d] = 0.f;

    GEMM_LOOP(g_w1f, g_xh, 0)

    // epilogue: bias + lrelu + fp16, transpose via smem, store [t][ch] plane
    __syncthreads();
    u16* ep = (u16*)dynsm;   // [128 cols(t)][132 rows(oc)] u16
    int gq = lid >> 2, cq = 2 * (lid & 3);
#pragma unroll
    for (int mf = 0; mf < 2; ++mf) {
        int r0 = wm * 32 + mf * 16 + gq, r1 = r0 + 8;
        int g0 = mt * 128 + r0, g1 = mt * 128 + r1;
        float bs0 = bC[g0] + bP[g0] + bF[g0];
        float bs1 = bC[g1] + bP[g1] + bF[g1];
#pragma unroll
        for (int nb = 0; nb < 8; ++nb) {
            int c = wn * 64 + nb * 8 + cq;
            const float* a = acc[mf][nb];
            ep[c * 132 + r0]       = h16(lrelu(a[0] + bs0));
            ep[(c + 1) * 132 + r0] = h16(lrelu(a[1] + bs0));
            ep[c * 132 + r1]       = h16(lrelu(a[2] + bs1));
            ep[(c + 1) * 132 + r1] = h16(lrelu(a[3] + bs1));
        }
    }
    __syncthreads();
    u32* yh = (u32*)g_yh;
    const u32* epu = (const u32*)dynsm;
    for (int i = tid; i < 128 * 64; i += NTHR) {
        int t = i >> 6, j = i & 63;
        yh[((size_t)(b * TL + t0 + t)) * 128 + mt * 64 + j] = epu[t * 66 + j];
    }
}

// ---------------- stage 2 GEMM kernel (conv3 + residual + write next-iter xh) ----------------
__global__ __launch_bounds__(NTHR, 2)
void k2(float* __restrict__ xo, const float* __restrict__ xres,
        const float* __restrict__ bA, int iter) {
    extern __shared__ __align__(1024) unsigned char dynsm[];

    const int tid = threadIdx.x, wid = tid >> 5, lid = tid & 31;
    const int wm = wid & 3, wn = wid >> 2;
    const int b = blockIdx.z, mt = blockIdx.y, t0 = blockIdx.x * 128;
    const u32 sb = sm2u(dynsm);
    const int wbase = ((iter * 2 + mt) * 12) * 1024;
    const u32 awoff = wm * 4096 + lid * 16;
    const int* s_ip = 0; const int* s_if = 0;   // unused in mode 1

    int boff[4], bsw[4];
    int ubsel = (lid >> 3) & 1;
    bfrag_setup(wn, lid, boff, bsw);

    float acc[2][8][4];
#pragma unroll
    for (int a = 0; a < 2; ++a)
#pragma unroll
        for (int c = 0; c < 8; ++c)
#pragma unroll
            for (int d = 0; d < 4; ++d) acc[a][c][d] = 0.f;

    GEMM_LOOP(g_w2f, g_yh, 1)

    // epilogue: bias + residual -> xo; also lrelu+fp16 transpose -> g_xh (next iter)
    __syncthreads();
    u16* ep = (u16*)dynsm;
    int gq = lid >> 2, cq = 2 * (lid & 3);
#pragma unroll
    for (int mf = 0; mf < 2; ++mf) {
        int r0 = wm * 32 + mf * 16 + gq, r1 = r0 + 8;
        int g0 = mt * 128 + r0, g1 = mt * 128 + r1;
        float bs0 = bA[g0], bs1 = bA[g1];
        size_t o0 = ((size_t)(b * CC + g0)) * TL + t0;
        size_t o1 = ((size_t)(b * CC + g1)) * TL + t0;
#pragma unroll
        for (int nb = 0; nb < 8; ++nb) {
            int c = wn * 64 + nb * 8 + cq;
            const float* a = acc[mf][nb];
            float2 r0v = *(const float2*)(xres + o0 + c);
            float2 r1v = *(const float2*)(xres + o1 + c);
            float2 v0, v1;
            v0.x = r0v.x + a[0] + bs0; v0.y = r0v.y + a[1] + bs0;
            v1.x = r1v.x + a[2] + bs1; v1.y = r1v.y + a[3] + bs1;
            *(float2*)(xo + o0 + c) = v0;
            *(float2*)(xo + o1 + c) = v1;
            ep[c * 132 + r0]       = h16(lrelu(v0.x));
            ep[(c + 1) * 132 + r0] = h16(lrelu(v0.y));
            ep[c * 132 + r1]       = h16(lrelu(v1.x));
            ep[(c + 1) * 132 + r1] = h16(lrelu(v1.y));
        }
    }
    __syncthreads();
    u32* xh = (u32*)g_xh;
    const u32* epu = (const u32*)dynsm;
    for (int i = tid; i < 128 * 64; i += NTHR) {
        int t = i >> 6, j = i & 63;
        xh[((size_t)(b * TL + t0 + t)) * 128 + mt * 64 + j] = epu[t * 66 + j];
    }
}

// ---------------- launch ----------------
extern "C" void kernel_launch(void* const* d_in, const int* in_sizes, int n_in,
                              void* d_out, int out_size) {
    const float* x  = (const float*)d_in[0];
    const float* d  = (const float*)d_in[1];
    const float* WC = (const float*)d_in[2];
    const float* bC = (const float*)d_in[3];
    const float* WP = (const float*)d_in[4];
    const float* bP = (const float*)d_in[5];
    const float* WF = (const float*)d_in[6];
    const float* bF = (const float*)d_in[7];
    const float* WA = (const float*)d_in[8];
    const float* bA = (const float*)d_in[9];
    float* xo = (float*)d_out;

    prep_w<<<576, 256>>>(WC, WP, WF, WA);

    cudaFuncSetAttribute((const void*)k1, cudaFuncAttributeMaxDynamicSharedMemorySize, DSMEM);
    cudaFuncSetAttribute((const void*)k2, cudaFuncAttributeMaxDynamicSharedMemorySize, DSMEM);

    dim3 gprex(TL / 32, BB);
    dim3 grid(TL / 128, 2, BB);
    const float dils[3] = {1.0f, 2.0f, 4.0f};
    prex<<<gprex, 256>>>(x);
    for (int i = 0; i < 3; ++i) {
        k1<<<grid, NTHR, DSMEM>>>(d, bC + i * 256, bP + i * 256, bF + i * 256, i, dils[i]);
        k2<<<grid, NTHR, DSMEM>>>(xo, (i == 0) ? x : xo, bA + i * 256, i);
    }
}